// round 10
// baseline (speedup 1.0000x reference)
#include <cuda_runtime.h>
#include <cuda_bf16.h>

// EGNN layer, B=2, N=16384, K=16, H=128.
// One CTA (128 threads) per FOUR nodes; warp g owns node g entirely.
// Edge-GEMM stages: each thread owns 4 channels (l, l+32, l+64, l+96) over
// all 16 edges of its node as 8 packed f32x2 pairs (k, k+8). Each broadcast
// LDS.128 of packed features feeds 16 FMA2 -> L1TEX wavefronts per node are
// cut ~33% vs the 2-warp/node version. The per-node smem tile is overwritten
// in place between stages (e1 over h_j, m_ij over e1, c1 over m_ij) with only
// __syncwarp -- no CTA barriers in the edge pipeline.
// Node MLP: thread t = channel t, 4-way node ILP sharing each weight load.

#define HDIM 128
#define BATCH 2
#define NPTS 16384
#define KNBR 16
#define NODES 4
#define NPAIR 8
#define NCH 4
#define STR2 132   // float2 stride per pair row (even => 16B-aligned rows)

typedef unsigned long long u64v;

__device__ __forceinline__ float silu_f(float v) {
    return v / (1.0f + __expf(-v));
}

__device__ __forceinline__ u64v pk2(float lo, float hi) {
    u64v r;
    asm("mov.b64 %0, {%1, %2};" : "=l"(r) : "f"(lo), "f"(hi));
    return r;
}
__device__ __forceinline__ void upk2(float& lo, float& hi, u64v v) {
    asm("mov.b64 {%0, %1}, %2;" : "=f"(lo), "=f"(hi) : "l"(v));
}
__device__ __forceinline__ u64v fma2(u64v a, u64v b, u64v c) {
    u64v d;
    asm("fma.rn.f32x2 %0, %1, %2, %3;" : "=l"(d) : "l"(a), "l"(b), "l"(c));
    return d;
}
__device__ __forceinline__ u64v silu2(u64v v) {
    float lo, hi;
    upk2(lo, hi, v);
    return pk2(silu_f(lo), silu_f(hi));
}

__global__ void __launch_bounds__(128)
egnn_layer_kernel(const float* __restrict__ h, const float* __restrict__ x,
                  const int* __restrict__ eidx,
                  const float* __restrict__ We1, const float* __restrict__ be1,
                  const float* __restrict__ We2, const float* __restrict__ be2,
                  const float* __restrict__ Wc1, const float* __restrict__ bc1,
                  const float* __restrict__ Wc2,
                  const float* __restrict__ Wn1, const float* __restrict__ bn1,
                  const float* __restrict__ Wn2, const float* __restrict__ bn2,
                  float* __restrict__ hout, float* __restrict__ xout)
{
    __shared__ __align__(16) float2 buf[NODES][NPAIR * STR2]; // h_j -> e1 -> m_ij -> c1
    __shared__ __align__(16) float shi[NODES][HDIM];
    __shared__ __align__(16) float msum[NODES][HDIM];
    __shared__ __align__(16) float n1b[NODES][HDIM];
    __shared__ float sq[NODES][KNBR];
    __shared__ float xdf[NODES][KNBR][3];
    __shared__ float cw[NODES][KNBR];
    __shared__ int   sidx[NODES][KNBR];
    __shared__ float sxi[NODES][3];

    const int t  = threadIdx.x;
    const int g  = t >> 5;           // warp = node slot
    const int l  = t & 31;
    const int n0 = blockIdx.x * NODES;
    const int node = n0 + g;
    const int b  = n0 / NPTS;        // NPTS % NODES == 0 -> same batch for all 4

    // ---- per-warp: node data ----
    {
        float4 hv = ((const float4*)(h + (long)node * HDIM))[l];
        *(float4*)&shi[g][4 * l] = hv;
    }
    if (l < KNBR) sidx[g][l] = eidx[(long)node * KNBR + l];
    if (l < 3)    sxi[g][l]  = x[(long)node * 3 + l];
    __syncwarp();

    if (l < KNBR) {
        int j = sidx[g][l];
        const float* xj = x + ((long)b * NPTS + j) * 3;
        float dx = sxi[g][0] - xj[0];
        float dy = sxi[g][1] - xj[1];
        float dz = sxi[g][2] - xj[2];
        xdf[g][l][0] = dx; xdf[g][l][1] = dy; xdf[g][l][2] = dz;
        sq[g][l] = dx*dx + dy*dy + dz*dz;
    }

    // ---- gather h_j PRE-PACKED: pair p row d holds {h_j(k=p)[d], h_j(k=p+8)[d]} ----
    #pragma unroll
    for (int p = 0; p < NPAIR; p++) {
        const float4* A  = (const float4*)(h + ((long)b * NPTS + sidx[g][p]) * HDIM);
        const float4* Bq = (const float4*)(h + ((long)b * NPTS + sidx[g][p + 8]) * HDIM);
        float4 a = A[l];
        float4 c = Bq[l];
        float2* dst = &buf[g][p * STR2 + 4 * l];
        dst[0] = make_float2(a.x, c.x);
        dst[1] = make_float2(a.y, c.y);
        dst[2] = make_float2(a.z, c.z);
        dst[3] = make_float2(a.w, c.w);
    }
    __syncwarp();

    u64v acc[NCH][NPAIR];

    // ---- edge MLP layer 1: e1 = silu([h_i, h_j, sq] @ We1 + be1) ----
    {
        // k-invariant h_i part
        float a0[NCH];
        #pragma unroll
        for (int c = 0; c < NCH; c++) a0[c] = be1[l + 32 * c];
        for (int d = 0; d < HDIM; d += 4) {
            float4 f = *(const float4*)&shi[g][d];
            #pragma unroll
            for (int c = 0; c < NCH; c++) {
                int ch = l + 32 * c;
                a0[c] = fmaf(f.x, We1[(d + 0) * HDIM + ch], a0[c]);
                a0[c] = fmaf(f.y, We1[(d + 1) * HDIM + ch], a0[c]);
                a0[c] = fmaf(f.z, We1[(d + 2) * HDIM + ch], a0[c]);
                a0[c] = fmaf(f.w, We1[(d + 3) * HDIM + ch], a0[c]);
            }
        }
        #pragma unroll
        for (int c = 0; c < NCH; c++) {
            u64v iv = pk2(a0[c], a0[c]);
            #pragma unroll
            for (int p = 0; p < NPAIR; p++) acc[c][p] = iv;
        }

        const float* W1b = We1 + HDIM * HDIM;  // rows 128..255 (h_j part)
        for (int d = 0; d < HDIM; d += 2) {
            u64v w0[NCH], w1[NCH];
            #pragma unroll
            for (int c = 0; c < NCH; c++) {
                float s0 = W1b[(d + 0) * HDIM + l + 32 * c];
                float s1 = W1b[(d + 1) * HDIM + l + 32 * c];
                w0[c] = pk2(s0, s0);
                w1[c] = pk2(s1, s1);
            }
            #pragma unroll
            for (int p = 0; p < NPAIR; p++) {
                ulonglong2 q = *(const ulonglong2*)&buf[g][p * STR2 + d];
                #pragma unroll
                for (int c = 0; c < NCH; c++) {
                    acc[c][p] = fma2(q.x, w0[c], acc[c][p]);
                    acc[c][p] = fma2(q.y, w1[c], acc[c][p]);
                }
            }
        }
        // sq row + silu
        #pragma unroll
        for (int c = 0; c < NCH; c++) {
            float wqs = We1[(2 * HDIM) * HDIM + l + 32 * c];
            u64v wq = pk2(wqs, wqs);
            #pragma unroll
            for (int p = 0; p < NPAIR; p++) {
                u64v sqp = pk2(sq[g][p], sq[g][p + 8]);
                acc[c][p] = silu2(fma2(sqp, wq, acc[c][p]));
            }
        }
        __syncwarp();   // all lanes done reading h_j tile
        #pragma unroll
        for (int c = 0; c < NCH; c++)
            #pragma unroll
            for (int p = 0; p < NPAIR; p++)
                *(u64v*)&buf[g][p * STR2 + l + 32 * c] = acc[c][p];   // e1 in place
        __syncwarp();
    }

    // ---- edge MLP layer 2: m_ij = silu(e1 @ We2 + be2) ----
    {
        #pragma unroll
        for (int c = 0; c < NCH; c++) {
            float bb = be2[l + 32 * c];
            u64v bv = pk2(bb, bb);
            #pragma unroll
            for (int p = 0; p < NPAIR; p++) acc[c][p] = bv;
        }
        for (int d = 0; d < HDIM; d += 2) {
            u64v w0[NCH], w1[NCH];
            #pragma unroll
            for (int c = 0; c < NCH; c++) {
                float s0 = We2[(d + 0) * HDIM + l + 32 * c];
                float s1 = We2[(d + 1) * HDIM + l + 32 * c];
                w0[c] = pk2(s0, s0);
                w1[c] = pk2(s1, s1);
            }
            #pragma unroll
            for (int p = 0; p < NPAIR; p++) {
                ulonglong2 q = *(const ulonglong2*)&buf[g][p * STR2 + d];
                #pragma unroll
                for (int c = 0; c < NCH; c++) {
                    acc[c][p] = fma2(q.x, w0[c], acc[c][p]);
                    acc[c][p] = fma2(q.y, w1[c], acc[c][p]);
                }
            }
        }
        // silu + m_i partial sums
        #pragma unroll
        for (int c = 0; c < NCH; c++) {
            float s = 0.0f;
            #pragma unroll
            for (int p = 0; p < NPAIR; p++) {
                acc[c][p] = silu2(acc[c][p]);
                float lo, hi;
                upk2(lo, hi, acc[c][p]);
                s += lo + hi;
            }
            msum[g][l + 32 * c] = s;
        }
        __syncwarp();   // all lanes done reading e1
        #pragma unroll
        for (int c = 0; c < NCH; c++)
            #pragma unroll
            for (int p = 0; p < NPAIR; p++)
                *(u64v*)&buf[g][p * STR2 + l + 32 * c] = acc[c][p];   // m_ij in place
        __syncwarp();
    }

    // ---- coord MLP layer 1: c1 = silu(m_ij @ Wc1 + bc1) ----
    {
        #pragma unroll
        for (int c = 0; c < NCH; c++) {
            float bb = bc1[l + 32 * c];
            u64v bv = pk2(bb, bb);
            #pragma unroll
            for (int p = 0; p < NPAIR; p++) acc[c][p] = bv;
        }
        for (int d = 0; d < HDIM; d += 2) {
            u64v w0[NCH], w1[NCH];
            #pragma unroll
            for (int c = 0; c < NCH; c++) {
                float s0 = Wc1[(d + 0) * HDIM + l + 32 * c];
                float s1 = Wc1[(d + 1) * HDIM + l + 32 * c];
                w0[c] = pk2(s0, s0);
                w1[c] = pk2(s1, s1);
            }
            #pragma unroll
            for (int p = 0; p < NPAIR; p++) {
                ulonglong2 q = *(const ulonglong2*)&buf[g][p * STR2 + d];
                #pragma unroll
                for (int c = 0; c < NCH; c++) {
                    acc[c][p] = fma2(q.x, w0[c], acc[c][p]);
                    acc[c][p] = fma2(q.y, w1[c], acc[c][p]);
                }
            }
        }
        #pragma unroll
        for (int c = 0; c < NCH; c++)
            #pragma unroll
            for (int p = 0; p < NPAIR; p++)
                acc[c][p] = silu2(acc[c][p]);
        __syncwarp();   // all lanes done reading m_ij
        #pragma unroll
        for (int c = 0; c < NCH; c++)
            #pragma unroll
            for (int p = 0; p < NPAIR; p++)
                *(u64v*)&buf[g][p * STR2 + l + 32 * c] = acc[c][p];   // c1 in place
        __syncwarp();
    }

    // ---- coord_w = c1 . Wc2 (warp reduce per packed pair) ----
    {
        float wv[NCH];
        #pragma unroll
        for (int c = 0; c < NCH; c++) wv[c] = Wc2[l + 32 * c];
        #pragma unroll
        for (int p = 0; p < NPAIR; p++) {
            float alo = 0.0f, ahi = 0.0f;
            #pragma unroll
            for (int c = 0; c < NCH; c++) {
                float2 v = buf[g][p * STR2 + l + 32 * c];
                alo = fmaf(v.x, wv[c], alo);
                ahi = fmaf(v.y, wv[c], ahi);
            }
            #pragma unroll
            for (int m = 16; m; m >>= 1) {
                alo += __shfl_xor_sync(0xffffffffu, alo, m);
                ahi += __shfl_xor_sync(0xffffffffu, ahi, m);
            }
            if (l == 0) { cw[g][p] = alo; cw[g][p + 8] = ahi; }
        }
        __syncwarp();
        if (l < 3) {
            float s = 0.0f;
            #pragma unroll
            for (int k = 0; k < KNBR; k++) s += xdf[g][k][l] * cw[g][k];
            xout[(long)node * 3 + l] = sxi[g][l] + s * (1.0f / (float)KNBR);
        }
    }

    __syncthreads();   // msum/shi of all 4 nodes visible to all warps

    // ---- node MLP: h_new = silu([h_i, m_i] @ Wn1 + bn1) @ Wn2 + bn2 + h_i ----
    {
        float na[NODES];
        #pragma unroll
        for (int nn = 0; nn < NODES; nn++) na[nn] = bn1[t];
        for (int d = 0; d < HDIM; d += 4) {
            float w0 = Wn1[(d + 0) * HDIM + t];
            float w1 = Wn1[(d + 1) * HDIM + t];
            float w2 = Wn1[(d + 2) * HDIM + t];
            float w3 = Wn1[(d + 3) * HDIM + t];
            #pragma unroll
            for (int nn = 0; nn < NODES; nn++) {
                float4 f = *(const float4*)&shi[nn][d];
                na[nn] = fmaf(f.x, w0, na[nn]);
                na[nn] = fmaf(f.y, w1, na[nn]);
                na[nn] = fmaf(f.z, w2, na[nn]);
                na[nn] = fmaf(f.w, w3, na[nn]);
            }
        }
        const float* Wn1b = Wn1 + HDIM * HDIM;
        for (int d = 0; d < HDIM; d += 4) {
            float w0 = Wn1b[(d + 0) * HDIM + t];
            float w1 = Wn1b[(d + 1) * HDIM + t];
            float w2 = Wn1b[(d + 2) * HDIM + t];
            float w3 = Wn1b[(d + 3) * HDIM + t];
            #pragma unroll
            for (int nn = 0; nn < NODES; nn++) {
                float4 f = *(const float4*)&msum[nn][d];
                na[nn] = fmaf(f.x, w0, na[nn]);
                na[nn] = fmaf(f.y, w1, na[nn]);
                na[nn] = fmaf(f.z, w2, na[nn]);
                na[nn] = fmaf(f.w, w3, na[nn]);
            }
        }
        #pragma unroll
        for (int nn = 0; nn < NODES; nn++) n1b[nn][t] = silu_f(na[nn]);
    }
    __syncthreads();
    {
        float oa[NODES];
        #pragma unroll
        for (int nn = 0; nn < NODES; nn++) oa[nn] = bn2[t] + shi[nn][t];
        for (int d = 0; d < HDIM; d += 4) {
            float w0 = Wn2[(d + 0) * HDIM + t];
            float w1 = Wn2[(d + 1) * HDIM + t];
            float w2 = Wn2[(d + 2) * HDIM + t];
            float w3 = Wn2[(d + 3) * HDIM + t];
            #pragma unroll
            for (int nn = 0; nn < NODES; nn++) {
                float4 f = *(const float4*)&n1b[nn][d];
                oa[nn] = fmaf(f.x, w0, oa[nn]);
                oa[nn] = fmaf(f.y, w1, oa[nn]);
                oa[nn] = fmaf(f.z, w2, oa[nn]);
                oa[nn] = fmaf(f.w, w3, oa[nn]);
            }
        }
        #pragma unroll
        for (int nn = 0; nn < NODES; nn++)
            hout[(long)(n0 + nn) * HDIM + t] = oa[nn];
    }
}

extern "C" void kernel_launch(void* const* d_in, const int* in_sizes, int n_in,
                              void* d_out, int out_size) {
    const float* h    = (const float*)d_in[0];
    const float* x    = (const float*)d_in[1];
    const int*   eidx = (const int*)d_in[2];
    const float* We1  = (const float*)d_in[3];
    const float* be1  = (const float*)d_in[4];
    const float* We2  = (const float*)d_in[5];
    const float* be2  = (const float*)d_in[6];
    const float* Wc1  = (const float*)d_in[7];
    const float* bc1  = (const float*)d_in[8];
    const float* Wc2  = (const float*)d_in[9];
    const float* Wn1  = (const float*)d_in[10];
    const float* bn1  = (const float*)d_in[11];
    const float* Wn2  = (const float*)d_in[12];
    const float* bn2  = (const float*)d_in[13];

    float* hout = (float*)d_out;                                  // (B,N,H)
    float* xout = (float*)d_out + (long)BATCH * NPTS * HDIM;      // (B,N,3)

    dim3 grid(BATCH * NPTS / NODES);
    dim3 block(128);
    egnn_layer_kernel<<<grid, block>>>(h, x, eidx,
                                       We1, be1, We2, be2,
                                       Wc1, bc1, Wc2,
                                       Wn1, bn1, Wn2, bn2,
                                       hout, xout);
}

// round 13
// speedup vs baseline: 1.1500x; 1.1500x over previous
#include <cuda_runtime.h>
#include <cuda_bf16.h>

// EGNN layer, B=2, N=16384, K=16, H=128.
// One CTA (128 threads) per FOUR nodes; warp g owns node g entirely.
// Edge-GEMM stages: thread l owns 4 CONTIGUOUS channels (4l..4l+3) over all
// 16 edges of its node as 8 packed f32x2 pairs (k, k+8). Contiguous channels
// let weight loads be LDG.128 (1 instr / 4 channels / row) and feature
// stores be STS.128 -- same L1 data wavefronts as the scalar version but
// ~900 fewer issue slots per warp per stage. __launch_bounds__(128,4) caps
// registers at 128 so 4 CTAs/SM fit (occupancy 25% vs 18.4%).
// Per-node smem tile overwritten in place between stages; __syncwarp only.

#define HDIM 128
#define BATCH 2
#define NPTS 16384
#define KNBR 16
#define NODES 4
#define NPAIR 8
#define NCH 4
#define STR2 132   // float2 stride per pair row (even => 16B-aligned rows)

typedef unsigned long long u64v;

__device__ __forceinline__ float silu_f(float v) {
    return v / (1.0f + __expf(-v));
}

__device__ __forceinline__ u64v pk2(float lo, float hi) {
    u64v r;
    asm("mov.b64 %0, {%1, %2};" : "=l"(r) : "f"(lo), "f"(hi));
    return r;
}
__device__ __forceinline__ void upk2(float& lo, float& hi, u64v v) {
    asm("mov.b64 {%0, %1}, %2;" : "=f"(lo), "=f"(hi) : "l"(v));
}
__device__ __forceinline__ u64v fma2(u64v a, u64v b, u64v c) {
    u64v d;
    asm("fma.rn.f32x2 %0, %1, %2, %3;" : "=l"(d) : "l"(a), "l"(b), "l"(c));
    return d;
}
__device__ __forceinline__ u64v silu2(u64v v) {
    float lo, hi;
    upk2(lo, hi, v);
    return pk2(silu_f(lo), silu_f(hi));
}

// One 128->128 edge-GEMM pass: acc[c][p] += sum_d feat2[p][d] * W[d][4l+c]
__device__ __forceinline__ void gemm_stage(const float* __restrict__ W,
                                           const float2* __restrict__ bufrow,
                                           int l, u64v acc[NCH][NPAIR]) {
    for (int d = 0; d < HDIM; d += 2) {
        float4 wa = *(const float4*)&W[(d + 0) * HDIM + 4 * l];
        float4 wb = *(const float4*)&W[(d + 1) * HDIM + 4 * l];
        u64v w0[NCH], w1[NCH];
        w0[0] = pk2(wa.x, wa.x); w0[1] = pk2(wa.y, wa.y);
        w0[2] = pk2(wa.z, wa.z); w0[3] = pk2(wa.w, wa.w);
        w1[0] = pk2(wb.x, wb.x); w1[1] = pk2(wb.y, wb.y);
        w1[2] = pk2(wb.z, wb.z); w1[3] = pk2(wb.w, wb.w);
        #pragma unroll
        for (int p = 0; p < NPAIR; p++) {
            ulonglong2 q = *(const ulonglong2*)&bufrow[p * STR2 + d];
            #pragma unroll
            for (int c = 0; c < NCH; c++) {
                acc[c][p] = fma2(q.x, w0[c], acc[c][p]);
                acc[c][p] = fma2(q.y, w1[c], acc[c][p]);
            }
        }
    }
}

// Store acc (channels 4l..4l+3, all pairs) into the tile as 2 STS.128/pair.
__device__ __forceinline__ void store_stage(float2* __restrict__ bufrow,
                                            int l, const u64v acc[NCH][NPAIR]) {
    #pragma unroll
    for (int p = 0; p < NPAIR; p++) {
        ulonglong2 s0, s1;
        s0.x = acc[0][p]; s0.y = acc[1][p];
        s1.x = acc[2][p]; s1.y = acc[3][p];
        *(ulonglong2*)&bufrow[p * STR2 + 4 * l]     = s0;
        *(ulonglong2*)&bufrow[p * STR2 + 4 * l + 2] = s1;
    }
}

__global__ void __launch_bounds__(128, 4)
egnn_layer_kernel(const float* __restrict__ h, const float* __restrict__ x,
                  const int* __restrict__ eidx,
                  const float* __restrict__ We1, const float* __restrict__ be1,
                  const float* __restrict__ We2, const float* __restrict__ be2,
                  const float* __restrict__ Wc1, const float* __restrict__ bc1,
                  const float* __restrict__ Wc2,
                  const float* __restrict__ Wn1, const float* __restrict__ bn1,
                  const float* __restrict__ Wn2, const float* __restrict__ bn2,
                  float* __restrict__ hout, float* __restrict__ xout)
{
    __shared__ __align__(16) float2 buf[NODES][NPAIR * STR2]; // h_j -> e1 -> m_ij -> c1
    __shared__ __align__(16) float shi[NODES][HDIM];
    __shared__ __align__(16) float msum[NODES][HDIM];
    __shared__ __align__(16) float n1b[NODES][HDIM];
    __shared__ float sq[NODES][KNBR];
    __shared__ float xdf[NODES][KNBR][3];
    __shared__ float cw[NODES][KNBR];
    __shared__ int   sidx[NODES][KNBR];
    __shared__ float sxi[NODES][3];

    const int t  = threadIdx.x;
    const int g  = t >> 5;           // warp = node slot
    const int l  = t & 31;
    const int n0 = blockIdx.x * NODES;
    const int node = n0 + g;
    const int b  = n0 / NPTS;        // NPTS % NODES == 0 -> same batch for all 4

    // ---- per-warp: node data ----
    {
        float4 hv = ((const float4*)(h + (long)node * HDIM))[l];
        *(float4*)&shi[g][4 * l] = hv;
    }
    if (l < KNBR) sidx[g][l] = eidx[(long)node * KNBR + l];
    if (l < 3)    sxi[g][l]  = x[(long)node * 3 + l];
    __syncwarp();

    if (l < KNBR) {
        int j = sidx[g][l];
        const float* xj = x + ((long)b * NPTS + j) * 3;
        float dx = sxi[g][0] - xj[0];
        float dy = sxi[g][1] - xj[1];
        float dz = sxi[g][2] - xj[2];
        xdf[g][l][0] = dx; xdf[g][l][1] = dy; xdf[g][l][2] = dz;
        sq[g][l] = dx*dx + dy*dy + dz*dz;
    }

    // ---- gather h_j PRE-PACKED: pair p row d holds {h_j(k=p)[d], h_j(k=p+8)[d]} ----
    #pragma unroll
    for (int p = 0; p < NPAIR; p++) {
        const float4* A  = (const float4*)(h + ((long)b * NPTS + sidx[g][p]) * HDIM);
        const float4* Bq = (const float4*)(h + ((long)b * NPTS + sidx[g][p + 8]) * HDIM);
        float4 a = A[l];
        float4 c = Bq[l];
        float2* dst = &buf[g][p * STR2 + 4 * l];
        dst[0] = make_float2(a.x, c.x);
        dst[1] = make_float2(a.y, c.y);
        dst[2] = make_float2(a.z, c.z);
        dst[3] = make_float2(a.w, c.w);
    }
    __syncwarp();

    u64v acc[NCH][NPAIR];

    // ---- edge MLP layer 1: e1 = silu([h_i, h_j, sq] @ We1 + be1) ----
    {
        // k-invariant h_i part (vectorized weight loads, channels 4l..4l+3)
        float4 bv = *(const float4*)&be1[4 * l];
        float a0[NCH] = {bv.x, bv.y, bv.z, bv.w};
        for (int d = 0; d < HDIM; d += 4) {
            float4 f  = *(const float4*)&shi[g][d];
            float4 r0 = *(const float4*)&We1[(d + 0) * HDIM + 4 * l];
            float4 r1 = *(const float4*)&We1[(d + 1) * HDIM + 4 * l];
            float4 r2 = *(const float4*)&We1[(d + 2) * HDIM + 4 * l];
            float4 r3 = *(const float4*)&We1[(d + 3) * HDIM + 4 * l];
            a0[0] = fmaf(f.x, r0.x, fmaf(f.y, r1.x, fmaf(f.z, r2.x, fmaf(f.w, r3.x, a0[0]))));
            a0[1] = fmaf(f.x, r0.y, fmaf(f.y, r1.y, fmaf(f.z, r2.y, fmaf(f.w, r3.y, a0[1]))));
            a0[2] = fmaf(f.x, r0.z, fmaf(f.y, r1.z, fmaf(f.z, r2.z, fmaf(f.w, r3.z, a0[2]))));
            a0[3] = fmaf(f.x, r0.w, fmaf(f.y, r1.w, fmaf(f.z, r2.w, fmaf(f.w, r3.w, a0[3]))));
        }
        #pragma unroll
        for (int c = 0; c < NCH; c++) {
            u64v iv = pk2(a0[c], a0[c]);
            #pragma unroll
            for (int p = 0; p < NPAIR; p++) acc[c][p] = iv;
        }

        gemm_stage(We1 + HDIM * HDIM, buf[g], l, acc);   // h_j part (rows 128..255)

        // sq row + silu
        float4 wq = *(const float4*)&We1[(2 * HDIM) * HDIM + 4 * l];
        u64v wqv[NCH] = {pk2(wq.x, wq.x), pk2(wq.y, wq.y), pk2(wq.z, wq.z), pk2(wq.w, wq.w)};
        #pragma unroll
        for (int p = 0; p < NPAIR; p++) {
            u64v sqp = pk2(sq[g][p], sq[g][p + 8]);
            #pragma unroll
            for (int c = 0; c < NCH; c++)
                acc[c][p] = silu2(fma2(sqp, wqv[c], acc[c][p]));
        }
        __syncwarp();   // all lanes done reading h_j tile
        store_stage(buf[g], l, acc);   // e1 in place
        __syncwarp();
    }

    // ---- edge MLP layer 2: m_ij = silu(e1 @ We2 + be2) ----
    {
        float4 bv = *(const float4*)&be2[4 * l];
        u64v b2[NCH] = {pk2(bv.x, bv.x), pk2(bv.y, bv.y), pk2(bv.z, bv.z), pk2(bv.w, bv.w)};
        #pragma unroll
        for (int c = 0; c < NCH; c++)
            #pragma unroll
            for (int p = 0; p < NPAIR; p++) acc[c][p] = b2[c];

        gemm_stage(We2, buf[g], l, acc);

        // silu + m_i partial sums (channels 4l..4l+3 -> contiguous msum store)
        float ms[NCH];
        #pragma unroll
        for (int c = 0; c < NCH; c++) {
            float s = 0.0f;
            #pragma unroll
            for (int p = 0; p < NPAIR; p++) {
                acc[c][p] = silu2(acc[c][p]);
                float lo, hi;
                upk2(lo, hi, acc[c][p]);
                s += lo + hi;
            }
            ms[c] = s;
        }
        *(float4*)&msum[g][4 * l] = make_float4(ms[0], ms[1], ms[2], ms[3]);
        __syncwarp();   // all lanes done reading e1
        store_stage(buf[g], l, acc);   // m_ij in place
        __syncwarp();
    }

    // ---- coord MLP layer 1: c1 = silu(m_ij @ Wc1 + bc1) ----
    {
        float4 bv = *(const float4*)&bc1[4 * l];
        u64v b1[NCH] = {pk2(bv.x, bv.x), pk2(bv.y, bv.y), pk2(bv.z, bv.z), pk2(bv.w, bv.w)};
        #pragma unroll
        for (int c = 0; c < NCH; c++)
            #pragma unroll
            for (int p = 0; p < NPAIR; p++) acc[c][p] = b1[c];

        gemm_stage(Wc1, buf[g], l, acc);

        #pragma unroll
        for (int c = 0; c < NCH; c++)
            #pragma unroll
            for (int p = 0; p < NPAIR; p++)
                acc[c][p] = silu2(acc[c][p]);
        __syncwarp();   // all lanes done reading m_ij
        store_stage(buf[g], l, acc);   // c1 in place
        __syncwarp();
    }

    // ---- coord_w = c1 . Wc2 (warp reduce per packed pair) ----
    {
        float4 wv = *(const float4*)&Wc2[4 * l];
        #pragma unroll
        for (int p = 0; p < NPAIR; p++) {
            float2 v0 = buf[g][p * STR2 + 4 * l + 0];
            float2 v1 = buf[g][p * STR2 + 4 * l + 1];
            float2 v2 = buf[g][p * STR2 + 4 * l + 2];
            float2 v3 = buf[g][p * STR2 + 4 * l + 3];
            float alo = v0.x * wv.x + v1.x * wv.y + v2.x * wv.z + v3.x * wv.w;
            float ahi = v0.y * wv.x + v1.y * wv.y + v2.y * wv.z + v3.y * wv.w;
            #pragma unroll
            for (int m = 16; m; m >>= 1) {
                alo += __shfl_xor_sync(0xffffffffu, alo, m);
                ahi += __shfl_xor_sync(0xffffffffu, ahi, m);
            }
            if (l == 0) { cw[g][p] = alo; cw[g][p + 8] = ahi; }
        }
        __syncwarp();
        if (l < 3) {
            float s = 0.0f;
            #pragma unroll
            for (int k = 0; k < KNBR; k++) s += xdf[g][k][l] * cw[g][k];
            xout[(long)node * 3 + l] = sxi[g][l] + s * (1.0f / (float)KNBR);
        }
    }

    __syncthreads();   // msum/shi of all 4 nodes visible to all warps

    // ---- node MLP: h_new = silu([h_i, m_i] @ Wn1 + bn1) @ Wn2 + bn2 + h_i ----
    {
        float na[NODES];
        #pragma unroll
        for (int nn = 0; nn < NODES; nn++) na[nn] = bn1[t];
        for (int d = 0; d < HDIM; d += 4) {
            float w0 = Wn1[(d + 0) * HDIM + t];
            float w1 = Wn1[(d + 1) * HDIM + t];
            float w2 = Wn1[(d + 2) * HDIM + t];
            float w3 = Wn1[(d + 3) * HDIM + t];
            #pragma unroll
            for (int nn = 0; nn < NODES; nn++) {
                float4 f = *(const float4*)&shi[nn][d];
                na[nn] = fmaf(f.x, w0, na[nn]);
                na[nn] = fmaf(f.y, w1, na[nn]);
                na[nn] = fmaf(f.z, w2, na[nn]);
                na[nn] = fmaf(f.w, w3, na[nn]);
            }
        }
        const float* Wn1b = Wn1 + HDIM * HDIM;
        for (int d = 0; d < HDIM; d += 4) {
            float w0 = Wn1b[(d + 0) * HDIM + t];
            float w1 = Wn1b[(d + 1) * HDIM + t];
            float w2 = Wn1b[(d + 2) * HDIM + t];
            float w3 = Wn1b[(d + 3) * HDIM + t];
            #pragma unroll
            for (int nn = 0; nn < NODES; nn++) {
                float4 f = *(const float4*)&msum[nn][d];
                na[nn] = fmaf(f.x, w0, na[nn]);
                na[nn] = fmaf(f.y, w1, na[nn]);
                na[nn] = fmaf(f.z, w2, na[nn]);
                na[nn] = fmaf(f.w, w3, na[nn]);
            }
        }
        #pragma unroll
        for (int nn = 0; nn < NODES; nn++) n1b[nn][t] = silu_f(na[nn]);
    }
    __syncthreads();
    {
        float oa[NODES];
        #pragma unroll
        for (int nn = 0; nn < NODES; nn++) oa[nn] = bn2[t] + shi[nn][t];
        for (int d = 0; d < HDIM; d += 4) {
            float w0 = Wn2[(d + 0) * HDIM + t];
            float w1 = Wn2[(d + 1) * HDIM + t];
            float w2 = Wn2[(d + 2) * HDIM + t];
            float w3 = Wn2[(d + 3) * HDIM + t];
            #pragma unroll
            for (int nn = 0; nn < NODES; nn++) {
                float4 f = *(const float4*)&n1b[nn][d];
                oa[nn] = fmaf(f.x, w0, oa[nn]);
                oa[nn] = fmaf(f.y, w1, oa[nn]);
                oa[nn] = fmaf(f.z, w2, oa[nn]);
                oa[nn] = fmaf(f.w, w3, oa[nn]);
            }
        }
        #pragma unroll
        for (int nn = 0; nn < NODES; nn++)
            hout[(long)(n0 + nn) * HDIM + t] = oa[nn];
    }
}

extern "C" void kernel_launch(void* const* d_in, const int* in_sizes, int n_in,
                              void* d_out, int out_size) {
    const float* h    = (const float*)d_in[0];
    const float* x    = (const float*)d_in[1];
    const int*   eidx = (const int*)d_in[2];
    const float* We1  = (const float*)d_in[3];
    const float* be1  = (const float*)d_in[4];
    const float* We2  = (const float*)d_in[5];
    const float* be2  = (const float*)d_in[6];
    const float* Wc1  = (const float*)d_in[7];
    const float* bc1  = (const float*)d_in[8];
    const float* Wc2  = (const float*)d_in[9];
    const float* Wn1  = (const float*)d_in[10];
    const float* bn1  = (const float*)d_in[11];
    const float* Wn2  = (const float*)d_in[12];
    const float* bn2  = (const float*)d_in[13];

    float* hout = (float*)d_out;                                  // (B,N,H)
    float* xout = (float*)d_out + (long)BATCH * NPTS * HDIM;      // (B,N,3)

    dim3 grid(BATCH * NPTS / NODES);
    dim3 block(128);
    egnn_layer_kernel<<<grid, block>>>(h, x, eidx,
                                       We1, be1, We2, be2,
                                       Wc1, bc1, Wc2,
                                       Wn1, bn1, Wn2, bn2,
                                       hout, xout);
}

// round 15
// speedup vs baseline: 1.1541x; 1.0036x over previous
#include <cuda_runtime.h>
#include <cuda_bf16.h>

// EGNN layer, B=2, N=16384, K=16, H=128.
// One CTA (128 threads) per FOUR nodes; warp g owns node g entirely.
// Edge-GEMM stages: thread l owns 4 CONTIGUOUS channels (4l..4l+3), LDG.128
// weights, STS.128 stores, packed f32x2 FMA over 8 edge pairs.
// THIS ROUND: shrink smem 42->39KB (STR2 132->130, n1b aliased into buf) so
// 4 CTAs/SM leave L1D = 228-156 = 72KB >= 64KB per-stage weight matrix ->
// weight LDG becomes L1-resident instead of thrashing to L2 (~250cyc).

#define HDIM 128
#define BATCH 2
#define NPTS 16384
#define KNBR 16
#define NODES 4
#define NPAIR 8
#define NCH 4
#define STR2 130   // float2 stride per pair row (even => 16B-aligned rows)

typedef unsigned long long u64v;

__device__ __forceinline__ float silu_f(float v) {
    return v / (1.0f + __expf(-v));
}

__device__ __forceinline__ u64v pk2(float lo, float hi) {
    u64v r;
    asm("mov.b64 %0, {%1, %2};" : "=l"(r) : "f"(lo), "f"(hi));
    return r;
}
__device__ __forceinline__ void upk2(float& lo, float& hi, u64v v) {
    asm("mov.b64 {%0, %1}, %2;" : "=f"(lo), "=f"(hi) : "l"(v));
}
__device__ __forceinline__ u64v fma2(u64v a, u64v b, u64v c) {
    u64v d;
    asm("fma.rn.f32x2 %0, %1, %2, %3;" : "=l"(d) : "l"(a), "l"(b), "l"(c));
    return d;
}
__device__ __forceinline__ u64v silu2(u64v v) {
    float lo, hi;
    upk2(lo, hi, v);
    return pk2(silu_f(lo), silu_f(hi));
}

// One 128->128 edge-GEMM pass: acc[c][p] += sum_d feat2[p][d] * W[d][4l+c]
__device__ __forceinline__ void gemm_stage(const float* __restrict__ W,
                                           const float2* __restrict__ bufrow,
                                           int l, u64v acc[NCH][NPAIR]) {
    for (int d = 0; d < HDIM; d += 2) {
        float4 wa = *(const float4*)&W[(d + 0) * HDIM + 4 * l];
        float4 wb = *(const float4*)&W[(d + 1) * HDIM + 4 * l];
        u64v w0[NCH], w1[NCH];
        w0[0] = pk2(wa.x, wa.x); w0[1] = pk2(wa.y, wa.y);
        w0[2] = pk2(wa.z, wa.z); w0[3] = pk2(wa.w, wa.w);
        w1[0] = pk2(wb.x, wb.x); w1[1] = pk2(wb.y, wb.y);
        w1[2] = pk2(wb.z, wb.z); w1[3] = pk2(wb.w, wb.w);
        #pragma unroll
        for (int p = 0; p < NPAIR; p++) {
            ulonglong2 q = *(const ulonglong2*)&bufrow[p * STR2 + d];
            #pragma unroll
            for (int c = 0; c < NCH; c++) {
                acc[c][p] = fma2(q.x, w0[c], acc[c][p]);
                acc[c][p] = fma2(q.y, w1[c], acc[c][p]);
            }
        }
    }
}

// Store acc (channels 4l..4l+3, all pairs) into the tile as 2 STS.128/pair.
__device__ __forceinline__ void store_stage(float2* __restrict__ bufrow,
                                            int l, const u64v acc[NCH][NPAIR]) {
    #pragma unroll
    for (int p = 0; p < NPAIR; p++) {
        ulonglong2 s0, s1;
        s0.x = acc[0][p]; s0.y = acc[1][p];
        s1.x = acc[2][p]; s1.y = acc[3][p];
        *(ulonglong2*)&bufrow[p * STR2 + 4 * l]     = s0;
        *(ulonglong2*)&bufrow[p * STR2 + 4 * l + 2] = s1;
    }
}

__global__ void __launch_bounds__(128, 4)
egnn_layer_kernel(const float* __restrict__ h, const float* __restrict__ x,
                  const int* __restrict__ eidx,
                  const float* __restrict__ We1, const float* __restrict__ be1,
                  const float* __restrict__ We2, const float* __restrict__ be2,
                  const float* __restrict__ Wc1, const float* __restrict__ bc1,
                  const float* __restrict__ Wc2,
                  const float* __restrict__ Wn1, const float* __restrict__ bn1,
                  const float* __restrict__ Wn2, const float* __restrict__ bn2,
                  float* __restrict__ hout, float* __restrict__ xout)
{
    __shared__ __align__(16) float2 buf[NODES][NPAIR * STR2]; // h_j -> e1 -> m_ij -> c1; later n1b
    __shared__ __align__(16) float shi[NODES][HDIM];
    __shared__ __align__(16) float msum[NODES][HDIM];
    __shared__ float sq[NODES][KNBR];
    __shared__ float xdf[NODES][KNBR][3];
    __shared__ float cw[NODES][KNBR];
    __shared__ int   sidx[NODES][KNBR];
    __shared__ float sxi[NODES][3];

    // n1b (node-MLP hidden, NODES x HDIM floats) aliases buf: buf's last use
    // is the coord_w stage, which completes before the __syncthreads() that
    // precedes node-MLP layer 1; another __syncthreads separates the n1b
    // write from its read.
    float (*n1b)[HDIM] = (float (*)[HDIM])(void*)buf;

    const int t  = threadIdx.x;
    const int g  = t >> 5;           // warp = node slot
    const int l  = t & 31;
    const int n0 = blockIdx.x * NODES;
    const int node = n0 + g;
    const int b  = n0 / NPTS;        // NPTS % NODES == 0 -> same batch for all 4

    // ---- per-warp: node data ----
    {
        float4 hv = ((const float4*)(h + (long)node * HDIM))[l];
        *(float4*)&shi[g][4 * l] = hv;
    }
    if (l < KNBR) sidx[g][l] = eidx[(long)node * KNBR + l];
    if (l < 3)    sxi[g][l]  = x[(long)node * 3 + l];
    __syncwarp();

    if (l < KNBR) {
        int j = sidx[g][l];
        const float* xj = x + ((long)b * NPTS + j) * 3;
        float dx = sxi[g][0] - xj[0];
        float dy = sxi[g][1] - xj[1];
        float dz = sxi[g][2] - xj[2];
        xdf[g][l][0] = dx; xdf[g][l][1] = dy; xdf[g][l][2] = dz;
        sq[g][l] = dx*dx + dy*dy + dz*dz;
    }

    // ---- gather h_j PRE-PACKED: pair p row d holds {h_j(k=p)[d], h_j(k=p+8)[d]} ----
    #pragma unroll
    for (int p = 0; p < NPAIR; p++) {
        const float4* A  = (const float4*)(h + ((long)b * NPTS + sidx[g][p]) * HDIM);
        const float4* Bq = (const float4*)(h + ((long)b * NPTS + sidx[g][p + 8]) * HDIM);
        float4 a = A[l];
        float4 c = Bq[l];
        float2* dst = &buf[g][p * STR2 + 4 * l];
        dst[0] = make_float2(a.x, c.x);
        dst[1] = make_float2(a.y, c.y);
        dst[2] = make_float2(a.z, c.z);
        dst[3] = make_float2(a.w, c.w);
    }
    __syncwarp();

    u64v acc[NCH][NPAIR];

    // ---- edge MLP layer 1: e1 = silu([h_i, h_j, sq] @ We1 + be1) ----
    {
        // k-invariant h_i part (vectorized weight loads, channels 4l..4l+3)
        float4 bv = *(const float4*)&be1[4 * l];
        float a0[NCH] = {bv.x, bv.y, bv.z, bv.w};
        for (int d = 0; d < HDIM; d += 4) {
            float4 f  = *(const float4*)&shi[g][d];
            float4 r0 = *(const float4*)&We1[(d + 0) * HDIM + 4 * l];
            float4 r1 = *(const float4*)&We1[(d + 1) * HDIM + 4 * l];
            float4 r2 = *(const float4*)&We1[(d + 2) * HDIM + 4 * l];
            float4 r3 = *(const float4*)&We1[(d + 3) * HDIM + 4 * l];
            a0[0] = fmaf(f.x, r0.x, fmaf(f.y, r1.x, fmaf(f.z, r2.x, fmaf(f.w, r3.x, a0[0]))));
            a0[1] = fmaf(f.x, r0.y, fmaf(f.y, r1.y, fmaf(f.z, r2.y, fmaf(f.w, r3.y, a0[1]))));
            a0[2] = fmaf(f.x, r0.z, fmaf(f.y, r1.z, fmaf(f.z, r2.z, fmaf(f.w, r3.z, a0[2]))));
            a0[3] = fmaf(f.x, r0.w, fmaf(f.y, r1.w, fmaf(f.z, r2.w, fmaf(f.w, r3.w, a0[3]))));
        }
        #pragma unroll
        for (int c = 0; c < NCH; c++) {
            u64v iv = pk2(a0[c], a0[c]);
            #pragma unroll
            for (int p = 0; p < NPAIR; p++) acc[c][p] = iv;
        }

        gemm_stage(We1 + HDIM * HDIM, buf[g], l, acc);   // h_j part (rows 128..255)

        // sq row + silu
        float4 wq = *(const float4*)&We1[(2 * HDIM) * HDIM + 4 * l];
        u64v wqv[NCH] = {pk2(wq.x, wq.x), pk2(wq.y, wq.y), pk2(wq.z, wq.z), pk2(wq.w, wq.w)};
        #pragma unroll
        for (int p = 0; p < NPAIR; p++) {
            u64v sqp = pk2(sq[g][p], sq[g][p + 8]);
            #pragma unroll
            for (int c = 0; c < NCH; c++)
                acc[c][p] = silu2(fma2(sqp, wqv[c], acc[c][p]));
        }
        __syncwarp();   // all lanes done reading h_j tile
        store_stage(buf[g], l, acc);   // e1 in place
        __syncwarp();
    }

    // ---- edge MLP layer 2: m_ij = silu(e1 @ We2 + be2) ----
    {
        float4 bv = *(const float4*)&be2[4 * l];
        u64v b2[NCH] = {pk2(bv.x, bv.x), pk2(bv.y, bv.y), pk2(bv.z, bv.z), pk2(bv.w, bv.w)};
        #pragma unroll
        for (int c = 0; c < NCH; c++)
            #pragma unroll
            for (int p = 0; p < NPAIR; p++) acc[c][p] = b2[c];

        gemm_stage(We2, buf[g], l, acc);

        // silu + m_i partial sums (channels 4l..4l+3 -> contiguous msum store)
        float ms[NCH];
        #pragma unroll
        for (int c = 0; c < NCH; c++) {
            float s = 0.0f;
            #pragma unroll
            for (int p = 0; p < NPAIR; p++) {
                acc[c][p] = silu2(acc[c][p]);
                float lo, hi;
                upk2(lo, hi, acc[c][p]);
                s += lo + hi;
            }
            ms[c] = s;
        }
        *(float4*)&msum[g][4 * l] = make_float4(ms[0], ms[1], ms[2], ms[3]);
        __syncwarp();   // all lanes done reading e1
        store_stage(buf[g], l, acc);   // m_ij in place
        __syncwarp();
    }

    // ---- coord MLP layer 1: c1 = silu(m_ij @ Wc1 + bc1) ----
    {
        float4 bv = *(const float4*)&bc1[4 * l];
        u64v b1[NCH] = {pk2(bv.x, bv.x), pk2(bv.y, bv.y), pk2(bv.z, bv.z), pk2(bv.w, bv.w)};
        #pragma unroll
        for (int c = 0; c < NCH; c++)
            #pragma unroll
            for (int p = 0; p < NPAIR; p++) acc[c][p] = b1[c];

        gemm_stage(Wc1, buf[g], l, acc);

        #pragma unroll
        for (int c = 0; c < NCH; c++)
            #pragma unroll
            for (int p = 0; p < NPAIR; p++)
                acc[c][p] = silu2(acc[c][p]);
        __syncwarp();   // all lanes done reading m_ij
        store_stage(buf[g], l, acc);   // c1 in place
        __syncwarp();
    }

    // ---- coord_w = c1 . Wc2 (warp reduce per packed pair) ----
    {
        float4 wv = *(const float4*)&Wc2[4 * l];
        #pragma unroll
        for (int p = 0; p < NPAIR; p++) {
            float2 v0 = buf[g][p * STR2 + 4 * l + 0];
            float2 v1 = buf[g][p * STR2 + 4 * l + 1];
            float2 v2 = buf[g][p * STR2 + 4 * l + 2];
            float2 v3 = buf[g][p * STR2 + 4 * l + 3];
            float alo = v0.x * wv.x + v1.x * wv.y + v2.x * wv.z + v3.x * wv.w;
            float ahi = v0.y * wv.x + v1.y * wv.y + v2.y * wv.z + v3.y * wv.w;
            #pragma unroll
            for (int m = 16; m; m >>= 1) {
                alo += __shfl_xor_sync(0xffffffffu, alo, m);
                ahi += __shfl_xor_sync(0xffffffffu, ahi, m);
            }
            if (l == 0) { cw[g][p] = alo; cw[g][p + 8] = ahi; }
        }
        __syncwarp();
        if (l < 3) {
            float s = 0.0f;
            #pragma unroll
            for (int k = 0; k < KNBR; k++) s += xdf[g][k][l] * cw[g][k];
            xout[(long)node * 3 + l] = sxi[g][l] + s * (1.0f / (float)KNBR);
        }
    }

    __syncthreads();   // msum/shi of all 4 nodes visible; buf dead -> n1b alias OK

    // ---- node MLP: h_new = silu([h_i, m_i] @ Wn1 + bn1) @ Wn2 + bn2 + h_i ----
    {
        float na[NODES];
        #pragma unroll
        for (int nn = 0; nn < NODES; nn++) na[nn] = bn1[t];
        for (int d = 0; d < HDIM; d += 4) {
            float w0 = Wn1[(d + 0) * HDIM + t];
            float w1 = Wn1[(d + 1) * HDIM + t];
            float w2 = Wn1[(d + 2) * HDIM + t];
            float w3 = Wn1[(d + 3) * HDIM + t];
            #pragma unroll
            for (int nn = 0; nn < NODES; nn++) {
                float4 f = *(const float4*)&shi[nn][d];
                na[nn] = fmaf(f.x, w0, na[nn]);
                na[nn] = fmaf(f.y, w1, na[nn]);
                na[nn] = fmaf(f.z, w2, na[nn]);
                na[nn] = fmaf(f.w, w3, na[nn]);
            }
        }
        const float* Wn1b = Wn1 + HDIM * HDIM;
        for (int d = 0; d < HDIM; d += 4) {
            float w0 = Wn1b[(d + 0) * HDIM + t];
            float w1 = Wn1b[(d + 1) * HDIM + t];
            float w2 = Wn1b[(d + 2) * HDIM + t];
            float w3 = Wn1b[(d + 3) * HDIM + t];
            #pragma unroll
            for (int nn = 0; nn < NODES; nn++) {
                float4 f = *(const float4*)&msum[nn][d];
                na[nn] = fmaf(f.x, w0, na[nn]);
                na[nn] = fmaf(f.y, w1, na[nn]);
                na[nn] = fmaf(f.z, w2, na[nn]);
                na[nn] = fmaf(f.w, w3, na[nn]);
            }
        }
        #pragma unroll
        for (int nn = 0; nn < NODES; nn++) n1b[nn][t] = silu_f(na[nn]);
    }
    __syncthreads();
    {
        float oa[NODES];
        #pragma unroll
        for (int nn = 0; nn < NODES; nn++) oa[nn] = bn2[t] + shi[nn][t];
        for (int d = 0; d < HDIM; d += 4) {
            float w0 = Wn2[(d + 0) * HDIM + t];
            float w1 = Wn2[(d + 1) * HDIM + t];
            float w2 = Wn2[(d + 2) * HDIM + t];
            float w3 = Wn2[(d + 3) * HDIM + t];
            #pragma unroll
            for (int nn = 0; nn < NODES; nn++) {
                float4 f = *(const float4*)&n1b[nn][d];
                oa[nn] = fmaf(f.x, w0, oa[nn]);
                oa[nn] = fmaf(f.y, w1, oa[nn]);
                oa[nn] = fmaf(f.z, w2, oa[nn]);
                oa[nn] = fmaf(f.w, w3, oa[nn]);
            }
        }
        #pragma unroll
        for (int nn = 0; nn < NODES; nn++)
            hout[(long)(n0 + nn) * HDIM + t] = oa[nn];
    }
}

extern "C" void kernel_launch(void* const* d_in, const int* in_sizes, int n_in,
                              void* d_out, int out_size) {
    const float* h    = (const float*)d_in[0];
    const float* x    = (const float*)d_in[1];
    const int*   eidx = (const int*)d_in[2];
    const float* We1  = (const float*)d_in[3];
    const float* be1  = (const float*)d_in[4];
    const float* We2  = (const float*)d_in[5];
    const float* be2  = (const float*)d_in[6];
    const float* Wc1  = (const float*)d_in[7];
    const float* bc1  = (const float*)d_in[8];
    const float* Wc2  = (const float*)d_in[9];
    const float* Wn1  = (const float*)d_in[10];
    const float* bn1  = (const float*)d_in[11];
    const float* Wn2  = (const float*)d_in[12];
    const float* bn2  = (const float*)d_in[13];

    float* hout = (float*)d_out;                                  // (B,N,H)
    float* xout = (float*)d_out + (long)BATCH * NPTS * HDIM;      // (B,N,3)

    dim3 grid(BATCH * NPTS / NODES);
    dim3 block(128);
    egnn_layer_kernel<<<grid, block>>>(h, x, eidx,
                                       We1, be1, We2, be2,
                                       Wc1, bc1, Wc2,
                                       Wn1, bn1, Wn2, bn2,
                                       hout, xout);
}